// round 4
// baseline (speedup 1.0000x reference)
#include <cuda_runtime.h>
#include <cuda_fp16.h>
#include <cstdint>

#define M_TOK 16384
#define KF    5760
#define KR    32
#define KEXT  5792
#define KPAD  5824          // 91 * 64
#define KT64  91
#define NOUT  640

// Scratch (device globals; .bss zero-init covers K padding in g_A cols 5792..5823)
__device__ __half g_A[(size_t)M_TOK * KPAD];    // [xq | t | 0pad]
__device__ __half g_Bt[(size_t)NOUT * KPAD];    // B transposed: [n][k]
__device__ __half g_pd[(size_t)KF * KR];        // proj_down f16

// ---------------- helpers ----------------
__device__ __forceinline__ uint32_t smem_u32(const void* p) {
    return (uint32_t)__cvta_generic_to_shared(p);
}
__device__ __forceinline__ void cp16(uint32_t dst_smem, const void* src_g) {
    asm volatile("cp.async.cg.shared.global [%0], [%1], 16;" :: "r"(dst_smem), "l"(src_g));
}
__device__ __forceinline__ void cp_commit() { asm volatile("cp.async.commit_group;"); }
__device__ __forceinline__ void ldmx4(uint32_t& r0, uint32_t& r1, uint32_t& r2, uint32_t& r3, uint32_t a) {
    asm volatile("ldmatrix.sync.aligned.m8n8.x4.shared.b16 {%0,%1,%2,%3}, [%4];"
                 : "=r"(r0), "=r"(r1), "=r"(r2), "=r"(r3) : "r"(a));
}
__device__ __forceinline__ void ldmx4t(uint32_t& r0, uint32_t& r1, uint32_t& r2, uint32_t& r3, uint32_t a) {
    asm volatile("ldmatrix.sync.aligned.m8n8.x4.trans.shared.b16 {%0,%1,%2,%3}, [%4];"
                 : "=r"(r0), "=r"(r1), "=r"(r2), "=r"(r3) : "r"(a));
}
__device__ __forceinline__ void mma16816(float c[4], const uint32_t a[4], const uint32_t b[2]) {
    asm volatile("mma.sync.aligned.m16n8k16.row.col.f32.f16.f16.f32 "
        "{%0,%1,%2,%3}, {%4,%5,%6,%7}, {%8,%9}, {%0,%1,%2,%3};"
        : "+f"(c[0]), "+f"(c[1]), "+f"(c[2]), "+f"(c[3])
        : "r"(a[0]), "r"(a[1]), "r"(a[2]), "r"(a[3]), "r"(b[0]), "r"(b[1]));
}
#define SW128(off) ((off) ^ (((off) >> 3) & 0x70))

// ---------------- K0: build g_Bt[n][k] = (qw*ws | pu^T | 0) f16 (smem transpose) ----------------
__global__ void __launch_bounds__(256) k_prep_t(const float* __restrict__ qw, const float* __restrict__ ws,
                                                const float* __restrict__ pu) {
    __shared__ __half ts[64 * 65];
    const int n0 = blockIdx.x * 64;   // 10 tiles
    const int k0 = blockIdx.y * 64;   // 91 tiles
    const int tid = threadIdx.x;
    #pragma unroll
    for (int i = 0; i < 16; i++) {
        int idx = tid + i * 256;
        int kr = idx >> 6, nc = idx & 63;
        int k = k0 + kr, n = n0 + nc;
        float v = 0.f;
        if (k < KF)        v = qw[(size_t)k * NOUT + n] * ws[(size_t)(k >> 6) * NOUT + n];
        else if (k < KEXT) v = pu[(size_t)(k - KF) * NOUT + n];
        ts[nc * 65 + kr] = __float2half(v);
    }
    __syncthreads();
    #pragma unroll
    for (int i = 0; i < 16; i++) {
        int idx = tid + i * 256;
        int nc = idx >> 6, kr = idx & 63;
        g_Bt[(size_t)(n0 + nc) * KPAD + k0 + kr] = ts[nc * 65 + kr];
    }
}

__global__ void k_pd(const float* __restrict__ pd) {
    int i = blockIdx.x * 256 + threadIdx.x;
    if (i < KF * KR) g_pd[i] = __float2half(pd[i]);
}

// ---------------- K1: fused quantize + low-rank. Reads x ONCE. ----------------
// CTA: 64 rows, 256 threads, 3-stage cp.async.
#define F_XS_F32   4096          // per stage: 64x64 f32
#define F_PDS_H    2560          // per stage: 64x40 halves
#define FUSE_SMEM  (3*F_XS_F32*4 + 3*F_PDS_H*2 + 64*72*2)

__global__ void __launch_bounds__(256) k_fuse(const float* __restrict__ x) {
    extern __shared__ char fsm[];
    float*  xs  = (float*)fsm;                                 // 3 stages
    __half* pds = (__half*)(fsm + 3 * F_XS_F32 * 4);           // 3 stages
    __half* xh  = (__half*)(fsm + 3 * F_XS_F32 * 4 + 3 * F_PDS_H * 2);  // 64x72

    const int tid = threadIdx.x;
    const int lane = tid & 31, warp = tid >> 5;
    const int m0 = blockIdx.x * 64;

    auto load_stage = [&](int kt) {
        int st = kt % 3;
        const float* xg = x + (size_t)m0 * KF + kt * 64;
        float* xd = xs + st * F_XS_F32;
        #pragma unroll
        for (int p = 0; p < 4; p++) {
            int id = tid + p * 256;
            int r = id >> 4, c = id & 15;
            cp16(smem_u32(xd + r * 64 + c * 4), xg + (size_t)r * KF + c * 4);
        }
        {
            int r = tid >> 2, c = tid & 3;
            cp16(smem_u32(pds + st * F_PDS_H + r * 40 + c * 8), g_pd + (size_t)(kt * 64 + r) * KR + c * 8);
        }
        cp_commit();
    };

    float acc[4][4];
    #pragma unroll
    for (int i = 0; i < 4; i++)
        #pragma unroll
        for (int j = 0; j < 4; j++) acc[i][j] = 0.f;

    load_stage(0); load_stage(1);

    for (int kt = 0; kt < 90; kt++) {
        int st = kt % 3;
        asm volatile("cp.async.wait_group 1;");
        __syncthreads();

        // quantize 8 rows per warp; write q*s to g_A, raw f16 to xh
        const float* xt = xs + st * F_XS_F32;
        #pragma unroll
        for (int i = 0; i < 8; i++) {
            int row = warp * 8 + i;
            float2 v = *(const float2*)(xt + row * 64 + lane * 2);
            float m = fmaxf(fabsf(v.x), fabsf(v.y));
            #pragma unroll
            for (int off = 16; off > 0; off >>= 1)
                m = fmaxf(m, __shfl_xor_sync(0xffffffffu, m, off));
            float s = fmaxf(__fdiv_rn(m, 7.0f), 1e-6f);
            float q0 = fminf(fmaxf(rintf(__fdiv_rn(v.x, s)), -8.0f), 7.0f);
            float q1 = fminf(fmaxf(rintf(__fdiv_rn(v.y, s)), -8.0f), 7.0f);
            *(__half2*)(g_A + (size_t)(m0 + row) * KPAD + kt * 64 + lane * 2) = __floats2half2_rn(q0 * s, q1 * s);
            *(__half2*)(xh + row * 72 + lane * 2) = __floats2half2_rn(v.x, v.y);
        }
        __syncthreads();

        if (kt + 2 < 90) load_stage(kt + 2);
        else cp_commit();

        if (warp < 4) {
            const __half* pdt = pds + st * F_PDS_H;
            #pragma unroll
            for (int kk = 0; kk < 4; kk++) {
                uint32_t a[4];
                ldmx4(a[0], a[1], a[2], a[3],
                      smem_u32(xh + (warp * 16 + (lane & 15)) * 72 + kk * 16 + (lane >> 4) * 8));
                uint32_t b[4][2];
                #pragma unroll
                for (int np = 0; np < 2; np++) {
                    uint32_t r0, r1, r2, r3;
                    ldmx4t(r0, r1, r2, r3,
                           smem_u32(pdt + (kk * 16 + (lane & 15)) * 40 + np * 16 + (lane >> 4) * 8));
                    b[np * 2][0] = r0; b[np * 2][1] = r1;
                    b[np * 2 + 1][0] = r2; b[np * 2 + 1][1] = r3;
                }
                #pragma unroll
                for (int ni = 0; ni < 4; ni++) mma16816(acc[ni], a, b[ni]);
            }
        }
        __syncthreads();
    }

    if (warp < 4) {
        #pragma unroll
        for (int ni = 0; ni < 4; ni++) {
            int c = ni * 8 + (lane & 3) * 2;
            int r = m0 + warp * 16 + (lane >> 2);
            g_A[(size_t)r * KPAD + KF + c]           = __float2half(acc[ni][0]);
            g_A[(size_t)r * KPAD + KF + c + 1]       = __float2half(acc[ni][1]);
            g_A[(size_t)(r + 8) * KPAD + KF + c]     = __float2half(acc[ni][2]);
            g_A[(size_t)(r + 8) * KPAD + KF + c + 1] = __float2half(acc[ni][3]);
        }
    }
}

// ---------------- K2: HMMA GEMM. BM=128, BN=128, BK=64, SW128 tiles, 3 stages ----------------
#define STAGE_B   16384                    // bytes per A (or B) stage: 128 rows x 128B
#define NST       3
#define GEMM_SMEM (2 * NST * STAGE_B)      // 96 KB

__global__ void __launch_bounds__(256, 2) k_gemm(const float* __restrict__ bias, float* __restrict__ out) {
    extern __shared__ char gsm[];
    const uint32_t sA = smem_u32(gsm);
    const uint32_t sB = sA + NST * STAGE_B;

    const int tid = threadIdx.x;
    const int lane = tid & 31, warp = tid >> 5;
    const int wm = warp >> 2, wn = warp & 3;       // 2 x 4 warp grid: 64 x 32 per warp
    const int m0 = blockIdx.y * 128;
    const int n0 = blockIdx.x * 128;

    float acc[4][4][4];
    #pragma unroll
    for (int i = 0; i < 4; i++)
        #pragma unroll
        for (int j = 0; j < 4; j++)
            #pragma unroll
            for (int k = 0; k < 4; k++) acc[i][j][k] = 0.f;

    auto load_stage = [&](int kt) {
        int s = kt % NST;
        const __half* Ag = g_A  + (size_t)m0 * KPAD + kt * 64;
        const __half* Bg = g_Bt + (size_t)n0 * KPAD + kt * 64;
        #pragma unroll
        for (int p = 0; p < 4; p++) {
            int id = tid + p * 256;          // 1024 chunks of 16B per matrix
            int r = id >> 3, j = id & 7;
            uint32_t sw = SW128((uint32_t)(r * 128 + j * 16));
            cp16(sA + s * STAGE_B + sw, Ag + (size_t)r * KPAD + j * 8);
            cp16(sB + s * STAGE_B + sw, Bg + (size_t)r * KPAD + j * 8);
        }
        cp_commit();
    };

    load_stage(0); load_stage(1);

    for (int kt = 0; kt < KT64; kt++) {
        asm volatile("cp.async.wait_group 1;");
        __syncthreads();
        if (kt + 2 < KT64) load_stage(kt + 2);
        else cp_commit();

        int s = kt % NST;
        const uint32_t Ab = sA + s * STAGE_B;
        const uint32_t Bb = sB + s * STAGE_B;
        #pragma unroll
        for (int kk = 0; kk < 4; kk++) {
            uint32_t a[4][4];
            #pragma unroll
            for (int mi = 0; mi < 4; mi++) {
                int row = wm * 64 + mi * 16 + (lane & 15);
                uint32_t off = (uint32_t)(row * 128 + kk * 32 + (lane >> 4) * 16);
                ldmx4(a[mi][0], a[mi][1], a[mi][2], a[mi][3], Ab + SW128(off));
            }
            uint32_t b[4][2];
            #pragma unroll
            for (int nb = 0; nb < 2; nb++) {
                int row = wn * 32 + nb * 16 + (lane & 15);
                uint32_t off = (uint32_t)(row * 128 + kk * 32 + (lane >> 4) * 16);
                uint32_t r0, r1, r2, r3;
                ldmx4(r0, r1, r2, r3, Bb + SW128(off));
                b[nb * 2][0] = r0;     b[nb * 2][1] = r2;      // n 0-7 of this 16: k0-7, k8-15
                b[nb * 2 + 1][0] = r1; b[nb * 2 + 1][1] = r3;  // n 8-15
            }
            #pragma unroll
            for (int mi = 0; mi < 4; mi++)
                #pragma unroll
                for (int ni = 0; ni < 4; ni++)
                    mma16816(acc[mi][ni], a[mi], b[ni]);
        }
    }

    // Epilogue: bias + transposed scatter store. out[((batch*640 + c) << 12) + l], m = batch*4096 + l
    #pragma unroll
    for (int ni = 0; ni < 4; ni++) {
        int cg = n0 + wn * 32 + ni * 8 + (lane & 3) * 2;
        float b0 = __ldg(bias + cg), b1 = __ldg(bias + cg + 1);
        #pragma unroll
        for (int mi = 0; mi < 4; mi++) {
            int r = m0 + wm * 64 + mi * 16 + (lane >> 2);
            int batch = r >> 12, l = r & 4095;
            size_t base = ((size_t)(batch * NOUT + cg) << 12) + l;
            out[base]            = acc[mi][ni][0] + b0;
            out[base + 4096]     = acc[mi][ni][1] + b1;
            out[base + 8]        = acc[mi][ni][2] + b0;
            out[base + 4096 + 8] = acc[mi][ni][3] + b1;
        }
    }
}

// ---------------- launch ----------------
extern "C" void kernel_launch(void* const* d_in, const int* in_sizes, int n_in,
                              void* d_out, int out_size) {
    const float* x    = (const float*)d_in[0];
    const float* qw   = (const float*)d_in[1];
    const float* ws   = (const float*)d_in[2];
    const float* pd   = (const float*)d_in[3];
    const float* pu   = (const float*)d_in[4];
    const float* bias = (const float*)d_in[5];
    float* out = (float*)d_out;

    cudaFuncSetAttribute(k_fuse, cudaFuncAttributeMaxDynamicSharedMemorySize, FUSE_SMEM);
    cudaFuncSetAttribute(k_gemm, cudaFuncAttributeMaxDynamicSharedMemorySize, GEMM_SMEM);

    dim3 gp(10, 91);
    k_prep_t<<<gp, 256>>>(qw, ws, pu);
    k_pd<<<(KF * KR + 255) / 256, 256>>>(pd);
    k_fuse<<<M_TOK / 64, 256, FUSE_SMEM>>>(x);
    dim3 gg(NOUT / 128, M_TOK / 128);
    k_gemm<<<gg, 256, GEMM_SMEM>>>(bias, out);
}

// round 5
// speedup vs baseline: 1.7352x; 1.7352x over previous
#include <cuda_runtime.h>
#include <cuda_fp16.h>
#include <cstdint>

#define M_TOK 16384
#define KF    5760
#define KR    32
#define KEXT  5792
#define NOUT  640

// Scratch (device globals: allocation-free per harness rules)
__device__ __half g_A[(size_t)M_TOK * KEXT];   // [xq | t]
__device__ __half g_B[(size_t)KEXT * NOUT];    // [wdeq ; pu]
__device__ __half g_pd[(size_t)KF * KR];       // proj_down f16

// ---------------- helpers ----------------
__device__ __forceinline__ uint32_t smem_u32(const void* p) {
    return (uint32_t)__cvta_generic_to_shared(p);
}
__device__ __forceinline__ void ldmx4(uint32_t& r0, uint32_t& r1, uint32_t& r2, uint32_t& r3, uint32_t a) {
    asm volatile("ldmatrix.sync.aligned.m8n8.x4.shared.b16 {%0,%1,%2,%3}, [%4];"
                 : "=r"(r0), "=r"(r1), "=r"(r2), "=r"(r3) : "r"(a));
}
__device__ __forceinline__ void ldmx4t(uint32_t& r0, uint32_t& r1, uint32_t& r2, uint32_t& r3, uint32_t a) {
    asm volatile("ldmatrix.sync.aligned.m8n8.x4.trans.shared.b16 {%0,%1,%2,%3}, [%4];"
                 : "=r"(r0), "=r"(r1), "=r"(r2), "=r"(r3) : "r"(a));
}
__device__ __forceinline__ void mma16816(float c[4], const uint32_t a[4], const uint32_t b[2]) {
    asm volatile("mma.sync.aligned.m16n8k16.row.col.f32.f16.f16.f32 "
        "{%0,%1,%2,%3}, {%4,%5,%6,%7}, {%8,%9}, {%0,%1,%2,%3};"
        : "+f"(c[0]), "+f"(c[1]), "+f"(c[2]), "+f"(c[3])
        : "r"(a[0]), "r"(a[1]), "r"(a[2]), "r"(a[3]), "r"(b[0]), "r"(b[1]));
}
__device__ __forceinline__ void cp16(uint32_t dst_smem, const void* src_g) {
    asm volatile("cp.async.cg.shared.global [%0], [%1], 16;" :: "r"(dst_smem), "l"(src_g));
}
__device__ __forceinline__ void cp_commit() { asm volatile("cp.async.commit_group;"); }

// ---------------- K0: build B_ext (wdeq | pu rows) + pd f16 ----------------
__global__ void k_prep(const float* __restrict__ qw, const float* __restrict__ ws,
                       const float* __restrict__ pu, const float* __restrict__ pd) {
    const int totB = KEXT * NOUT;
    const int tot  = totB + KF * KR;
    for (int idx = blockIdx.x * blockDim.x + threadIdx.x; idx < tot; idx += gridDim.x * blockDim.x) {
        if (idx < totB) {
            int k = idx / NOUT, n = idx - k * NOUT;
            float v;
            if (k < KF) v = qw[(size_t)k * NOUT + n] * ws[(size_t)(k >> 6) * NOUT + n];
            else        v = pu[(size_t)(k - KF) * NOUT + n];
            g_B[idx] = __float2half(v);
        } else {
            int j = idx - totB;
            g_pd[j] = __float2half(pd[j]);
        }
    }
}

// ---------------- K1: fused quantize + low-rank (reads x once) ----------------
// CTA: 64 rows, 256 threads (8 warps), 3-stage cp.async.
// Warp w: quantizes rows w*8..w*8+7; MMA tile rows (w>>1)*16, rank cols (w&1)*16.
#define F_XS_F32   4096          // per stage: 64x64 f32
#define F_PDS_H    2560          // per stage: 64x40 halves
#define FUSE_SMEM  (3*F_XS_F32*4 + 3*F_PDS_H*2 + 64*72*2)

__global__ void __launch_bounds__(256) k_fuse(const float* __restrict__ x) {
    extern __shared__ char fsm[];
    float*  xs  = (float*)fsm;                                          // 3 stages 64x64 f32
    __half* pds = (__half*)(fsm + 3 * F_XS_F32 * 4);                    // 3 stages 64x40 h
    __half* xh  = (__half*)(fsm + 3 * F_XS_F32 * 4 + 3 * F_PDS_H * 2);  // 64x72 h

    const int tid = threadIdx.x;
    const int lane = tid & 31, warp = tid >> 5;
    const int m0 = blockIdx.x * 64;
    const int oct = lane & 7;                 // octet id within quant row
    const int wm = (warp >> 1) * 16;          // mma row tile
    const int wn = (warp & 1) * 16;           // mma rank-col tile

    auto load_stage = [&](int kt) {
        int st = kt % 3;
        const float* xg = x + (size_t)m0 * KF + kt * 64;
        float* xd = xs + st * F_XS_F32;
        #pragma unroll
        for (int p = 0; p < 4; p++) {
            int id = tid + p * 256;
            int r = id >> 4, c = id & 15;
            cp16(smem_u32(xd + r * 64 + c * 4), xg + (size_t)r * KF + c * 4);
        }
        {
            int r = tid >> 2, c = tid & 3;
            cp16(smem_u32(pds + st * F_PDS_H + r * 40 + c * 8), g_pd + (size_t)(kt * 64 + r) * KR + c * 8);
        }
        cp_commit();
    };

    float acc[2][4];
    #pragma unroll
    for (int i = 0; i < 2; i++)
        #pragma unroll
        for (int j = 0; j < 4; j++) acc[i][j] = 0.f;

    load_stage(0); load_stage(1);

    for (int kt = 0; kt < 90; kt++) {
        int st = kt % 3;
        asm volatile("cp.async.wait_group 1;");
        __syncthreads();

        // quantize: 2 passes x 4 rows; lane handles 8 elems (two float4 128B apart)
        const float* xt = xs + st * F_XS_F32;
        #pragma unroll
        for (int pass = 0; pass < 2; pass++) {
            int row = warp * 8 + pass * 4 + (lane >> 3);
            const float* xr = xt + row * 64;
            float4 v0 = *(const float4*)(xr + oct * 4);
            float4 v1 = *(const float4*)(xr + 32 + oct * 4);
            float m = fmaxf(fmaxf(fmaxf(fabsf(v0.x), fabsf(v0.y)), fmaxf(fabsf(v0.z), fabsf(v0.w))),
                            fmaxf(fmaxf(fabsf(v1.x), fabsf(v1.y)), fmaxf(fabsf(v1.z), fabsf(v1.w))));
            #pragma unroll
            for (int off = 4; off > 0; off >>= 1)
                m = fmaxf(m, __shfl_xor_sync(0xffffffffu, m, off));
            float s = fmaxf(__fdiv_rn(m, 7.0f), 1e-6f);
            float q0 = fminf(fmaxf(rintf(__fdiv_rn(v0.x, s)), -8.f), 7.f) * s;
            float q1 = fminf(fmaxf(rintf(__fdiv_rn(v0.y, s)), -8.f), 7.f) * s;
            float q2 = fminf(fmaxf(rintf(__fdiv_rn(v0.z, s)), -8.f), 7.f) * s;
            float q3 = fminf(fmaxf(rintf(__fdiv_rn(v0.w, s)), -8.f), 7.f) * s;
            float q4 = fminf(fmaxf(rintf(__fdiv_rn(v1.x, s)), -8.f), 7.f) * s;
            float q5 = fminf(fmaxf(rintf(__fdiv_rn(v1.y, s)), -8.f), 7.f) * s;
            float q6 = fminf(fmaxf(rintf(__fdiv_rn(v1.z, s)), -8.f), 7.f) * s;
            float q7 = fminf(fmaxf(rintf(__fdiv_rn(v1.w, s)), -8.f), 7.f) * s;
            __half* ga = g_A + (size_t)(m0 + row) * KEXT + kt * 64;
            *(__half2*)(ga + oct * 4)          = __floats2half2_rn(q0, q1);
            *(__half2*)(ga + oct * 4 + 2)      = __floats2half2_rn(q2, q3);
            *(__half2*)(ga + 32 + oct * 4)     = __floats2half2_rn(q4, q5);
            *(__half2*)(ga + 32 + oct * 4 + 2) = __floats2half2_rn(q6, q7);
            __half* xr16 = xh + row * 72;
            *(__half2*)(xr16 + oct * 4)          = __floats2half2_rn(v0.x, v0.y);
            *(__half2*)(xr16 + oct * 4 + 2)      = __floats2half2_rn(v0.z, v0.w);
            *(__half2*)(xr16 + 32 + oct * 4)     = __floats2half2_rn(v1.x, v1.y);
            *(__half2*)(xr16 + 32 + oct * 4 + 2) = __floats2half2_rn(v1.z, v1.w);
        }
        __syncthreads();

        if (kt + 2 < 90) load_stage(kt + 2);
        else cp_commit();

        // rank-32 MMA: all 8 warps, each m16 x n16
        const __half* pdt = pds + st * F_PDS_H;
        #pragma unroll
        for (int kk = 0; kk < 4; kk++) {
            uint32_t a[4];
            ldmx4(a[0], a[1], a[2], a[3],
                  smem_u32(xh + (wm + (lane & 15)) * 72 + kk * 16 + (lane >> 4) * 8));
            uint32_t r0, r1, r2, r3;
            ldmx4t(r0, r1, r2, r3,
                   smem_u32(pdt + (kk * 16 + (lane & 15)) * 40 + wn + (lane >> 4) * 8));
            uint32_t b0[2] = {r0, r1}, b1[2] = {r2, r3};
            mma16816(acc[0], a, b0);
            mma16816(acc[1], a, b1);
        }
    }

    #pragma unroll
    for (int nh = 0; nh < 2; nh++) {
        int c = wn + nh * 8 + (lane & 3) * 2;
        int r = m0 + wm + (lane >> 2);
        g_A[(size_t)r * KEXT + KF + c]           = __float2half(acc[nh][0]);
        g_A[(size_t)r * KEXT + KF + c + 1]       = __float2half(acc[nh][1]);
        g_A[(size_t)(r + 8) * KEXT + KF + c]     = __float2half(acc[nh][2]);
        g_A[(size_t)(r + 8) * KEXT + KF + c + 1] = __float2half(acc[nh][3]);
    }
}

// ---------------- K2: main GEMM (R2 version: BK=32, 4 stages, padded strides) ----------------
#define ASTRIDE 40
#define BSTRIDE 136
#define A_STAGE (128 * ASTRIDE)
#define B_STAGE (32 * BSTRIDE)
#define SMEM_HALVES (4 * A_STAGE + 4 * B_STAGE)
#define SMEM_BYTES (SMEM_HALVES * 2)

__global__ void __launch_bounds__(256, 2) k_gemm(const float* __restrict__ bias, float* __restrict__ out) {
    extern __shared__ __half smem[];
    __half* As = smem;
    __half* Bs = smem + 4 * A_STAGE;

    const int tid = threadIdx.x;
    const int lane = tid & 31, warp = tid >> 5;
    const int wm = warp >> 2, wn = warp & 3;       // 2 x 4 warp grid
    const int m0 = blockIdx.y * 128;
    const int n0 = blockIdx.x * 128;

    float acc[4][4][4];
    #pragma unroll
    for (int i = 0; i < 4; i++)
        #pragma unroll
        for (int j = 0; j < 4; j++)
            #pragma unroll
            for (int k = 0; k < 4; k++) acc[i][j][k] = 0.f;

    auto issue = [&](int kt) {
        int s = kt & 3;
        const __half* Ag = g_A + (size_t)m0 * KEXT + kt * 32;
        __half* Asd = As + s * A_STAGE;
        #pragma unroll
        for (int p = 0; p < 2; p++) {
            int cid = tid + p * 256;
            int r = cid >> 2, c4 = cid & 3;
            cp16(smem_u32(Asd + r * ASTRIDE + c4 * 8), Ag + (size_t)r * KEXT + c4 * 8);
        }
        const __half* Bg = g_B + (size_t)(kt * 32) * NOUT + n0;
        __half* Bsd = Bs + s * B_STAGE;
        #pragma unroll
        for (int p = 0; p < 2; p++) {
            int cid = tid + p * 256;
            int r = cid >> 4, c16 = cid & 15;
            cp16(smem_u32(Bsd + r * BSTRIDE + c16 * 8), Bg + (size_t)r * NOUT + c16 * 8);
        }
        cp_commit();
    };

    const int KT = KEXT / 32;  // 181
    issue(0); issue(1); issue(2);

    for (int kt = 0; kt < KT; kt++) {
        asm volatile("cp.async.wait_group 2;");
        __syncthreads();
        if (kt + 3 < KT) issue(kt + 3);
        else cp_commit();

        int s = kt & 3;
        const __half* Asd = As + s * A_STAGE;
        const __half* Bsd = Bs + s * B_STAGE;
        #pragma unroll
        for (int kk = 0; kk < 2; kk++) {
            uint32_t a[4][4];
            #pragma unroll
            for (int mi = 0; mi < 4; mi++)
                ldmx4(a[mi][0], a[mi][1], a[mi][2], a[mi][3],
                      smem_u32(Asd + (wm * 64 + mi * 16 + (lane & 15)) * ASTRIDE + kk * 16 + (lane >> 4) * 8));
            uint32_t b[4][2];
            #pragma unroll
            for (int np = 0; np < 2; np++) {
                uint32_t r0, r1, r2, r3;
                ldmx4t(r0, r1, r2, r3,
                       smem_u32(Bsd + (kk * 16 + (lane & 15)) * BSTRIDE + wn * 32 + np * 16 + (lane >> 4) * 8));
                b[np * 2][0] = r0; b[np * 2][1] = r1;
                b[np * 2 + 1][0] = r2; b[np * 2 + 1][1] = r3;
            }
            #pragma unroll
            for (int mi = 0; mi < 4; mi++)
                #pragma unroll
                for (int ni = 0; ni < 4; ni++)
                    mma16816(acc[mi][ni], a[mi], b[ni]);
        }
    }

    // Epilogue: bias + transposed scatter store
    #pragma unroll
    for (int ni = 0; ni < 4; ni++) {
        int cg = n0 + wn * 32 + ni * 8 + (lane & 3) * 2;
        float b0 = __ldg(bias + cg), b1 = __ldg(bias + cg + 1);
        #pragma unroll
        for (int mi = 0; mi < 4; mi++) {
            int r = m0 + wm * 64 + mi * 16 + (lane >> 2);
            int batch = r >> 12, l = r & 4095;
            size_t base = ((size_t)(batch * NOUT + cg) << 12) + l;
            out[base]            = acc[mi][ni][0] + b0;
            out[base + 4096]     = acc[mi][ni][1] + b1;
            out[base + 8]        = acc[mi][ni][2] + b0;
            out[base + 4096 + 8] = acc[mi][ni][3] + b1;
        }
    }
}

// ---------------- launch ----------------
extern "C" void kernel_launch(void* const* d_in, const int* in_sizes, int n_in,
                              void* d_out, int out_size) {
    const float* x    = (const float*)d_in[0];
    const float* qw   = (const float*)d_in[1];
    const float* ws   = (const float*)d_in[2];
    const float* pd   = (const float*)d_in[3];
    const float* pu   = (const float*)d_in[4];
    const float* bias = (const float*)d_in[5];
    float* out = (float*)d_out;

    cudaFuncSetAttribute(k_fuse, cudaFuncAttributeMaxDynamicSharedMemorySize, FUSE_SMEM);
    cudaFuncSetAttribute(k_gemm, cudaFuncAttributeMaxDynamicSharedMemorySize, SMEM_BYTES);

    k_prep<<<4096, 256>>>(qw, ws, pu, pd);
    k_fuse<<<M_TOK / 64, 256, FUSE_SMEM>>>(x);
    dim3 g3(NOUT / 128, M_TOK / 128);
    k_gemm<<<g3, 256, SMEM_BYTES>>>(bias, out);
}

// round 6
// speedup vs baseline: 1.7385x; 1.0019x over previous
#include <cuda_runtime.h>
#include <cuda_fp16.h>
#include <cstdint>

#define M_TOK 16384
#define KF    5760
#define KR    32
#define KEXT  5792
#define KPAD  5824           // 91 * 64 (zero-padded tail from .bss)
#define KT64  91
#define NOUT  640

// Scratch (device globals: allocation-free per harness rules)
__device__ __half g_A[(size_t)M_TOK * KPAD];   // [xq | t | 0pad]
__device__ __half g_B[(size_t)KPAD * NOUT];    // [wdeq ; pu ; 0pad]
__device__ __half g_pd[(size_t)KF * KR];       // proj_down f16

// ---------------- helpers ----------------
__device__ __forceinline__ uint32_t smem_u32(const void* p) {
    return (uint32_t)__cvta_generic_to_shared(p);
}
__device__ __forceinline__ void ldmx4(uint32_t& r0, uint32_t& r1, uint32_t& r2, uint32_t& r3, uint32_t a) {
    asm volatile("ldmatrix.sync.aligned.m8n8.x4.shared.b16 {%0,%1,%2,%3}, [%4];"
                 : "=r"(r0), "=r"(r1), "=r"(r2), "=r"(r3) : "r"(a));
}
__device__ __forceinline__ void ldmx4t(uint32_t& r0, uint32_t& r1, uint32_t& r2, uint32_t& r3, uint32_t a) {
    asm volatile("ldmatrix.sync.aligned.m8n8.x4.trans.shared.b16 {%0,%1,%2,%3}, [%4];"
                 : "=r"(r0), "=r"(r1), "=r"(r2), "=r"(r3) : "r"(a));
}
__device__ __forceinline__ void mma16816(float c[4], const uint32_t a[4], const uint32_t b[2]) {
    asm volatile("mma.sync.aligned.m16n8k16.row.col.f32.f16.f16.f32 "
        "{%0,%1,%2,%3}, {%4,%5,%6,%7}, {%8,%9}, {%0,%1,%2,%3};"
        : "+f"(c[0]), "+f"(c[1]), "+f"(c[2]), "+f"(c[3])
        : "r"(a[0]), "r"(a[1]), "r"(a[2]), "r"(a[3]), "r"(b[0]), "r"(b[1]));
}
__device__ __forceinline__ void cp16(uint32_t dst_smem, const void* src_g) {
    asm volatile("cp.async.cg.shared.global [%0], [%1], 16;" :: "r"(dst_smem), "l"(src_g));
}
__device__ __forceinline__ void cp_commit() { asm volatile("cp.async.commit_group;"); }

// ---------------- K0: build B_ext (wdeq | pu rows) + pd f16 ----------------
__global__ void k_prep(const float* __restrict__ qw, const float* __restrict__ ws,
                       const float* __restrict__ pu, const float* __restrict__ pd) {
    const int totB = KEXT * NOUT;
    const int tot  = totB + KF * KR;
    for (int idx = blockIdx.x * blockDim.x + threadIdx.x; idx < tot; idx += gridDim.x * blockDim.x) {
        if (idx < totB) {
            int k = idx / NOUT, n = idx - k * NOUT;
            float v;
            if (k < KF) v = qw[(size_t)k * NOUT + n] * ws[(size_t)(k >> 6) * NOUT + n];
            else        v = pu[(size_t)(k - KF) * NOUT + n];
            g_B[idx] = __float2half(v);
        } else {
            int j = idx - totB;
            g_pd[j] = __float2half(pd[j]);
        }
    }
}

// ---------------- K1: fused quantize + low-rank (reads x once) ----------------
#define F_XS_F32   4096          // per stage: 64x64 f32
#define F_PDS_H    2560          // per stage: 64x40 halves
#define FUSE_SMEM  (3*F_XS_F32*4 + 3*F_PDS_H*2 + 64*72*2)

__global__ void __launch_bounds__(256) k_fuse(const float* __restrict__ x) {
    extern __shared__ char fsm[];
    float*  xs  = (float*)fsm;
    __half* pds = (__half*)(fsm + 3 * F_XS_F32 * 4);
    __half* xh  = (__half*)(fsm + 3 * F_XS_F32 * 4 + 3 * F_PDS_H * 2);

    const int tid = threadIdx.x;
    const int lane = tid & 31, warp = tid >> 5;
    const int m0 = blockIdx.x * 64;
    const int oct = lane & 7;
    const int wm = (warp >> 1) * 16;
    const int wn = (warp & 1) * 16;

    auto load_stage = [&](int kt) {
        int st = kt % 3;
        const float* xg = x + (size_t)m0 * KF + kt * 64;
        float* xd = xs + st * F_XS_F32;
        #pragma unroll
        for (int p = 0; p < 4; p++) {
            int id = tid + p * 256;
            int r = id >> 4, c = id & 15;
            cp16(smem_u32(xd + r * 64 + c * 4), xg + (size_t)r * KF + c * 4);
        }
        {
            int r = tid >> 2, c = tid & 3;
            cp16(smem_u32(pds + st * F_PDS_H + r * 40 + c * 8), g_pd + (size_t)(kt * 64 + r) * KR + c * 8);
        }
        cp_commit();
    };

    float acc[2][4];
    #pragma unroll
    for (int i = 0; i < 2; i++)
        #pragma unroll
        for (int j = 0; j < 4; j++) acc[i][j] = 0.f;

    load_stage(0); load_stage(1);

    for (int kt = 0; kt < 90; kt++) {
        int st = kt % 3;
        asm volatile("cp.async.wait_group 1;");
        __syncthreads();

        const float* xt = xs + st * F_XS_F32;
        #pragma unroll
        for (int pass = 0; pass < 2; pass++) {
            int row = warp * 8 + pass * 4 + (lane >> 3);
            const float* xr = xt + row * 64;
            float4 v0 = *(const float4*)(xr + oct * 4);
            float4 v1 = *(const float4*)(xr + 32 + oct * 4);
            float m = fmaxf(fmaxf(fmaxf(fabsf(v0.x), fabsf(v0.y)), fmaxf(fabsf(v0.z), fabsf(v0.w))),
                            fmaxf(fmaxf(fabsf(v1.x), fabsf(v1.y)), fmaxf(fabsf(v1.z), fabsf(v1.w))));
            #pragma unroll
            for (int off = 4; off > 0; off >>= 1)
                m = fmaxf(m, __shfl_xor_sync(0xffffffffu, m, off));
            float s = fmaxf(__fdiv_rn(m, 7.0f), 1e-6f);
            float q0 = fminf(fmaxf(rintf(__fdiv_rn(v0.x, s)), -8.f), 7.f) * s;
            float q1 = fminf(fmaxf(rintf(__fdiv_rn(v0.y, s)), -8.f), 7.f) * s;
            float q2 = fminf(fmaxf(rintf(__fdiv_rn(v0.z, s)), -8.f), 7.f) * s;
            float q3 = fminf(fmaxf(rintf(__fdiv_rn(v0.w, s)), -8.f), 7.f) * s;
            float q4 = fminf(fmaxf(rintf(__fdiv_rn(v1.x, s)), -8.f), 7.f) * s;
            float q5 = fminf(fmaxf(rintf(__fdiv_rn(v1.y, s)), -8.f), 7.f) * s;
            float q6 = fminf(fmaxf(rintf(__fdiv_rn(v1.z, s)), -8.f), 7.f) * s;
            float q7 = fminf(fmaxf(rintf(__fdiv_rn(v1.w, s)), -8.f), 7.f) * s;
            __half* ga = g_A + (size_t)(m0 + row) * KPAD + kt * 64;
            *(__half2*)(ga + oct * 4)          = __floats2half2_rn(q0, q1);
            *(__half2*)(ga + oct * 4 + 2)      = __floats2half2_rn(q2, q3);
            *(__half2*)(ga + 32 + oct * 4)     = __floats2half2_rn(q4, q5);
            *(__half2*)(ga + 32 + oct * 4 + 2) = __floats2half2_rn(q6, q7);
            __half* xr16 = xh + row * 72;
            *(__half2*)(xr16 + oct * 4)          = __floats2half2_rn(v0.x, v0.y);
            *(__half2*)(xr16 + oct * 4 + 2)      = __floats2half2_rn(v0.z, v0.w);
            *(__half2*)(xr16 + 32 + oct * 4)     = __floats2half2_rn(v1.x, v1.y);
            *(__half2*)(xr16 + 32 + oct * 4 + 2) = __floats2half2_rn(v1.z, v1.w);
        }
        __syncthreads();

        if (kt + 2 < 90) load_stage(kt + 2);
        else cp_commit();

        const __half* pdt = pds + st * F_PDS_H;
        #pragma unroll
        for (int kk = 0; kk < 4; kk++) {
            uint32_t a[4];
            ldmx4(a[0], a[1], a[2], a[3],
                  smem_u32(xh + (wm + (lane & 15)) * 72 + kk * 16 + (lane >> 4) * 8));
            uint32_t r0, r1, r2, r3;
            ldmx4t(r0, r1, r2, r3,
                   smem_u32(pdt + (kk * 16 + (lane & 15)) * 40 + wn + (lane >> 4) * 8));
            uint32_t b0[2] = {r0, r1}, b1[2] = {r2, r3};
            mma16816(acc[0], a, b0);
            mma16816(acc[1], a, b1);
        }
    }

    #pragma unroll
    for (int nh = 0; nh < 2; nh++) {
        int c = wn + nh * 8 + (lane & 3) * 2;
        int r = m0 + wm + (lane >> 2);
        g_A[(size_t)r * KPAD + KF + c]           = __float2half(acc[nh][0]);
        g_A[(size_t)r * KPAD + KF + c + 1]       = __float2half(acc[nh][1]);
        g_A[(size_t)(r + 8) * KPAD + KF + c]     = __float2half(acc[nh][2]);
        g_A[(size_t)(r + 8) * KPAD + KF + c + 1] = __float2half(acc[nh][3]);
    }
}

// ---------------- K2: GEMM. BM=128 BN=128 BK=64, 3 stages, frag ping-pong ----------------
#define ASTR 72
#define BSTR 136
#define A_ST (128 * ASTR)     // 9216 halves
#define B_ST (64 * BSTR)      // 8704 halves
#define NST  3
#define GEMM_SMEM ((NST * (A_ST + B_ST)) * 2)   // 107520 B

__global__ void __launch_bounds__(256, 2) k_gemm(const float* __restrict__ bias, float* __restrict__ out) {
    extern __shared__ __half smem[];
    __half* As = smem;
    __half* Bs = smem + NST * A_ST;

    const int tid = threadIdx.x;
    const int lane = tid & 31, warp = tid >> 5;
    const int wm = warp >> 2, wn = warp & 3;       // 2 x 4 warp grid: 64 x 32 per warp
    const int m0 = blockIdx.y * 128;
    const int n0 = blockIdx.x * 128;

    float acc[4][4][4];
    #pragma unroll
    for (int i = 0; i < 4; i++)
        #pragma unroll
        for (int j = 0; j < 4; j++)
            #pragma unroll
            for (int k = 0; k < 4; k++) acc[i][j][k] = 0.f;

    auto issue = [&](int kt) {
        int s = kt % NST;
        const __half* Ag = g_A + (size_t)m0 * KPAD + kt * 64;
        __half* Asd = As + s * A_ST;
        #pragma unroll
        for (int p = 0; p < 4; p++) {
            int cid = tid + p * 256;               // 1024 chunks
            int r = cid >> 3, c = cid & 7;
            cp16(smem_u32(Asd + r * ASTR + c * 8), Ag + (size_t)r * KPAD + c * 8);
        }
        const __half* Bg = g_B + (size_t)(kt * 64) * NOUT + n0;
        __half* Bsd = Bs + s * B_ST;
        #pragma unroll
        for (int p = 0; p < 4; p++) {
            int cid = tid + p * 256;               // 1024 chunks
            int r = cid >> 4, c = cid & 15;
            cp16(smem_u32(Bsd + r * BSTR + c * 8), Bg + (size_t)r * NOUT + c * 8);
        }
        cp_commit();
    };

    issue(0); issue(1);

    // fragment ping-pong buffers
    uint32_t af[2][4][4];
    uint32_t bf[2][4][2];

    #pragma unroll 1
    for (int kt = 0; kt < KT64; kt++) {
        asm volatile("cp.async.wait_group 1;");
        __syncthreads();
        if (kt + 2 < KT64) issue(kt + 2);
        else cp_commit();

        int s = kt % NST;
        const uint32_t Ab = smem_u32(As + s * A_ST) + ((wm * 64 + (lane & 15)) * ASTR + (lane >> 4) * 8) * 2;
        const uint32_t Bb = smem_u32(Bs + s * B_ST) + (((lane & 15)) * BSTR + wn * 32 + (lane >> 4) * 8) * 2;

        // preload kk=0 into buffer 0
        #pragma unroll
        for (int mi = 0; mi < 4; mi++)
            ldmx4(af[0][mi][0], af[0][mi][1], af[0][mi][2], af[0][mi][3],
                  Ab + (mi * 16 * ASTR) * 2);
        #pragma unroll
        for (int np = 0; np < 2; np++) {
            uint32_t r0, r1, r2, r3;
            ldmx4t(r0, r1, r2, r3, Bb + (np * 16) * 2);
            bf[0][np * 2][0] = r0;     bf[0][np * 2][1] = r1;
            bf[0][np * 2 + 1][0] = r2; bf[0][np * 2 + 1][1] = r3;
        }

        #pragma unroll
        for (int kk = 0; kk < 4; kk++) {
            int cur = kk & 1, nxt = cur ^ 1;
            if (kk < 3) {
                // prefetch kk+1 fragments into the other buffer (overlaps with MMAs below)
                #pragma unroll
                for (int mi = 0; mi < 4; mi++)
                    ldmx4(af[nxt][mi][0], af[nxt][mi][1], af[nxt][mi][2], af[nxt][mi][3],
                          Ab + (mi * 16 * ASTR + (kk + 1) * 16) * 2);
                #pragma unroll
                for (int np = 0; np < 2; np++) {
                    uint32_t r0, r1, r2, r3;
                    ldmx4t(r0, r1, r2, r3, Bb + ((kk + 1) * 16 * BSTR + np * 16) * 2);
                    bf[nxt][np * 2][0] = r0;     bf[nxt][np * 2][1] = r1;
                    bf[nxt][np * 2 + 1][0] = r2; bf[nxt][np * 2 + 1][1] = r3;
                }
            }
            #pragma unroll
            for (int mi = 0; mi < 4; mi++)
                #pragma unroll
                for (int ni = 0; ni < 4; ni++)
                    mma16816(acc[mi][ni], af[cur][mi], bf[cur][ni]);
        }
    }

    // Epilogue: bias + transposed scatter store
    #pragma unroll
    for (int ni = 0; ni < 4; ni++) {
        int cg = n0 + wn * 32 + ni * 8 + (lane & 3) * 2;
        float b0 = __ldg(bias + cg), b1 = __ldg(bias + cg + 1);
        #pragma unroll
        for (int mi = 0; mi < 4; mi++) {
            int r = m0 + wm * 64 + mi * 16 + (lane >> 2);
            int batch = r >> 12, l = r & 4095;
            size_t base = ((size_t)(batch * NOUT + cg) << 12) + l;
            out[base]            = acc[mi][ni][0] + b0;
            out[base + 4096]     = acc[mi][ni][1] + b1;
            out[base + 8]        = acc[mi][ni][2] + b0;
            out[base + 4096 + 8] = acc[mi][ni][3] + b1;
        }
    }
}

// ---------------- launch ----------------
extern "C" void kernel_launch(void* const* d_in, const int* in_sizes, int n_in,
                              void* d_out, int out_size) {
    const float* x    = (const float*)d_in[0];
    const float* qw   = (const float*)d_in[1];
    const float* ws   = (const float*)d_in[2];
    const float* pd   = (const float*)d_in[3];
    const float* pu   = (const float*)d_in[4];
    const float* bias = (const float*)d_in[5];
    float* out = (float*)d_out;

    cudaFuncSetAttribute(k_fuse, cudaFuncAttributeMaxDynamicSharedMemorySize, FUSE_SMEM);
    cudaFuncSetAttribute(k_gemm, cudaFuncAttributeMaxDynamicSharedMemorySize, GEMM_SMEM);

    k_prep<<<4096, 256>>>(qw, ws, pu, pd);
    k_fuse<<<M_TOK / 64, 256, FUSE_SMEM>>>(x);
    dim3 g3(NOUT / 128, M_TOK / 128);
    k_gemm<<<g3, 256, GEMM_SMEM>>>(bias, out);
}